// round 10
// baseline (speedup 1.0000x reference)
#include <cuda_runtime.h>

// BrockHommes: B=8192 rows, T=4096 strictly-sequential steps, one row per
// thread, grid=256 x block=32 (solo warp per SMSP; R8 proved co-residency
// slows the per-warp chain and wall = T * per-warp step time).
//
// Loop-carried chain this round (only thing that matters; instr count is
// nearly free per R6-R9 calibration):
//   ex2 stagger(16) -> ex2 lat(16) -> den(+4) -> rcp(17) -> q'-fma(4) -> clamp(5)
// The old tail rcp -> UN -> q-mul -> clamp is shortened by distributing the
// post-rcp fma over regimes:
//   q'_k = (num*rd + esr)*E_k = fma(num*E_k, rd, esr*E_k)
// with num*E_k and esr*E_k computed in the rcp shadow.
//
// Algebra (exact up to fp rounding):
//  * softmax shift-invariance, regime-0 shift: p_0 = 1, p_k = 2^(U*E'_k),
//    E'_k = bl*(d_k-d_0) = bgd_k*x3 + bcd_k,  U = x1 - R*x2,
//    bl = beta*log2e (absorbed into E' constants).
//  * overflow guard: A_k = fmin(q_k, 88)  (load-bearing: some rows saturate).
//  * x_t = num*rd + es;  U_{t+1} = num*rd + esr,  esr = fma(-R, x1, es).

#define B_CONST 8192
#define T_CONST 4096

__device__ __forceinline__ float ex2a(float x){float y;asm("ex2.approx.f32 %0, %1;":"=f"(y):"f"(x));return y;}
__device__ __forceinline__ float rcpa(float x){float y;asm("rcp.approx.f32 %0, %1;":"=f"(y):"f"(x));return y;}

// One step.
// In:  A1..A3 = clamped exponents for THIS step (carried);
//      X1,X2 = x_{t-1},x_{t-2}; ES = eps_t*sigma/R.
// Out: XT = x_t; B1..B3 = clamped exponents for NEXT step.
#define BH_STEP(ES, X1, X2, A1,A2,A3, XT, B1,B2,B3) \
  { \
    /* ---- chain head: exps immediately ---- */ \
    float p1 = ex2a(A1); \
    float p2 = ex2a(A2); \
    float p3 = ex2a(A3); \
    /* ---- shadow work (fills MUFU latency) ---- */ \
    float m0 = fmaf(gi0, X1, bi0); \
    float m1 = fmaf(gi1, X1, bi1); \
    float m2 = fmaf(gi2, X1, bi2); \
    float m3 = fmaf(gi3, X1, bi3); \
    float esr = fmaf(nR, X1, ES); \
    float E1 = fmaf(bgd1, X2, bcd1); \
    float E2 = fmaf(bgd2, X2, bcd2); \
    float E3 = fmaf(bgd3, X2, bcd3); \
    /* ---- arrival-ordered reductions ---- */ \
    float den = ((1.0f + p1) + p2) + p3; \
    float num = fmaf(p3, m3, fmaf(p2, m2, fmaf(p1, m1, m0))); \
    /* ---- rcp shadow: distribute U' over regimes ---- */ \
    float nE1 = num * E1; \
    float nE2 = num * E2; \
    float nE3 = num * E3; \
    float w1 = esr * E1; \
    float w2 = esr * E2; \
    float w3 = esr * E3; \
    float rd = rcpa(den); \
    XT = fmaf(num, rd, ES); \
    B1 = fminf(fmaf(nE1, rd, w1), 88.0f); \
    B2 = fminf(fmaf(nE2, rd, w2), 88.0f); \
    B3 = fminf(fmaf(nE3, rd, w3), 88.0f); \
  }

__global__ void __launch_bounds__(32, 1)
bh_kernel(const float* __restrict__ theta,
          const float* __restrict__ eps,
          float* __restrict__ out)
{
    const int b = blockIdx.x * 32 + threadIdx.x;   // 0..8191

    const float* th = theta + (size_t)b * 11;
    const float L2E = 1.44269504088896340736f;

    const float g0 = th[1], g1 = th[2], g2 = th[3], g3 = th[4];
    const float c0 = th[5], c1 = th[6], c2 = th[7], c3 = th[8];
    const float R    = 1.0f + th[10];
    const float iR   = 1.0f / R;                  // one-time accurate div
    const float bl   = th[0] * L2E;               // beta * log2(e)
    const float nR   = -R;
    const float sg   = th[9] * iR;                // sigma / R
    const float gi0 = g0 * iR, gi1 = g1 * iR, gi2 = g2 * iR, gi3 = g3 * iR;
    const float bi0 = c0 * iR, bi1 = c1 * iR, bi2 = c2 * iR, bi3 = c3 * iR;
    // E'-prep constants: E'_k = bl*(g_k - g0)*x3 + bl*(c_k - c0)
    const float bgd1 = bl * (g1 - g0), bgd2 = bl * (g2 - g0), bgd3 = bl * (g3 - g0);
    const float bcd1 = bl * (c1 - c0), bcd2 = bl * (c2 - c0), bcd3 = bl * (c3 - c0);

    const float4* ep4 = reinterpret_cast<const float4*>(eps + (size_t)b * T_CONST);
    float4*       o4  = reinterpret_cast<float4*>(out + (size_t)b * T_CONST);
    const int T4 = T_CONST / 4;

    // carried state: x's and the pre-clamped exponents for the first step.
    // t=0: x1=x2=0, U=0 -> q_k = 0 -> A_k = 0 (p_k = 1, softmax of zeros).
    float x1 = 0.f, x2 = 0.f;
    float A1 = 0.f, A2 = 0.f, A3 = 0.f;

    // distance-2 prefetch
    float4 bufA = ep4[0];
    float4 bufB = ep4[1];

    for (int i = 0; i < T4; ++i) {
        float4 ev = bufA;
        bufA = bufB;
        int nidx = (i + 2 < T4) ? (i + 2) : (T4 - 1);
        bufB = ep4[nidx];

        float es0 = ev.x * sg, es1 = ev.y * sg, es2 = ev.z * sg, es3 = ev.w * sg;

        float xt0, xt1, xt2, xt3;
        float Ab1, Ab2, Ab3;   // exps after step0
        float Ac1, Ac2, Ac3;   // after step1
        float Ad1, Ad2, Ad3;   // after step2

        BH_STEP(es0, x1,  x2,  A1,A2,A3,    xt0, Ab1,Ab2,Ab3);
        BH_STEP(es1, xt0, x1,  Ab1,Ab2,Ab3, xt1, Ac1,Ac2,Ac3);
        BH_STEP(es2, xt1, xt0, Ac1,Ac2,Ac3, xt2, Ad1,Ad2,Ad3);
        BH_STEP(es3, xt2, xt1, Ad1,Ad2,Ad3, xt3, A1,A2,A3);

        x2 = xt2;
        x1 = xt3;

        o4[i] = make_float4(xt0, xt1, xt2, xt3);
    }
}

extern "C" void kernel_launch(void* const* d_in, const int* in_sizes, int n_in,
                              void* d_out, int out_size)
{
    const float* theta = (const float*)d_in[0];   // (B, 11) float32
    const float* eps   = (const float*)d_in[1];   // (B, T)  float32
    float*       out   = (float*)d_out;           // (B, T)  float32

    bh_kernel<<<B_CONST / 32, 32>>>(theta, eps, out);
}

// round 11
// speedup vs baseline: 1.2439x; 1.2439x over previous
#include <cuda_runtime.h>

// BrockHommes: B=8192 rows, T=4096 strictly-sequential steps, one row per
// thread, grid=256 x block=32 (solo warp per SMSP — R8 proved co-residency
// slows the per-warp chain and wall = T * per-warp step time).
//
// In-order issue calibration (R10): instructions placed before a chain op
// delay its ISSUE. So rcpa(den) is emitted immediately after den's final add;
// the num chain and the nE/w muls run inside rcp's 17-cycle shadow.
//
// Loop-carried chain: ex2 stagger(16) + ex2 lat(16) + den(4) + rcp(17)
//                     + B=fma(4) + clamp(5)  ~= 57 cyc model.
//
// Algebra (exact up to fp rounding):
//  * softmax shift-invariance, regime-0 shift: p_0 = 1, p_k = 2^(U*E'_k),
//    E'_k = bl*(d_k-d_0) = bgd_k*x3 + bcd_k,  U = x1 - R*x2,
//    bl = beta*log2e absorbed into the E' constants.
//  * next exponents fused through the reciprocal:
//      A'_k = U'*E'_k = (num*rd + esr)*E_k = fma(num*E_k, rd, esr*E_k)
//    with num*E_k, esr*E_k computed in the rcp shadow.
//  * overflow guard: A_k = fmin(.,88) (load-bearing: saturated rows exist).
//  * x_t = num*rd + es;  esr = fma(-R, x1, es).

#define B_CONST 8192
#define T_CONST 4096

__device__ __forceinline__ float ex2a(float x){float y;asm("ex2.approx.f32 %0, %1;":"=f"(y):"f"(x));return y;}
__device__ __forceinline__ float rcpa(float x){float y;asm("rcp.approx.f32 %0, %1;":"=f"(y):"f"(x));return y;}

// One step.
// In:  A1..A3 = clamped exponents for THIS step (carried);
//      X1,X2 = x_{t-1},x_{t-2}; ES = eps_t*sigma/R.
// Out: XT = x_t; B1..B3 = clamped exponents for NEXT step.
#define BH_STEP(ES, X1, X2, A1,A2,A3, XT, B1,B2,B3) \
  { \
    /* ---- chain head: exps first ---- */ \
    float p1 = ex2a(A1); \
    float p2 = ex2a(A2); \
    float p3 = ex2a(A3); \
    /* ---- shadow work (fills ex2 latency) ---- */ \
    float m0 = fmaf(gi0, X1, bi0); \
    float m1 = fmaf(gi1, X1, bi1); \
    float m2 = fmaf(gi2, X1, bi2); \
    float m3 = fmaf(gi3, X1, bi3); \
    float esr = fmaf(nR, X1, ES); \
    float E1 = fmaf(bgd1, X2, bcd1); \
    float E2 = fmaf(bgd2, X2, bcd2); \
    float E3 = fmaf(bgd3, X2, bcd3); \
    float w1 = esr * E1; \
    float w2 = esr * E2; \
    float w3 = esr * E3; \
    /* ---- den, then rcp ISSUES IMMEDIATELY (nothing between) ---- */ \
    float den = ((1.0f + p1) + p2) + p3; \
    float rd = rcpa(den); \
    /* ---- rcp shadow: num chain + regime products ---- */ \
    float num = fmaf(p3, m3, fmaf(p2, m2, fmaf(p1, m1, m0))); \
    float nE1 = num * E1; \
    float nE2 = num * E2; \
    float nE3 = num * E3; \
    /* ---- tail ---- */ \
    XT = fmaf(num, rd, ES); \
    B1 = fminf(fmaf(nE1, rd, w1), 88.0f); \
    B2 = fminf(fmaf(nE2, rd, w2), 88.0f); \
    B3 = fminf(fmaf(nE3, rd, w3), 88.0f); \
  }

__global__ void __launch_bounds__(32, 1)
bh_kernel(const float* __restrict__ theta,
          const float* __restrict__ eps,
          float* __restrict__ out)
{
    const int b = blockIdx.x * 32 + threadIdx.x;   // 0..8191

    const float* th = theta + (size_t)b * 11;
    const float L2E = 1.44269504088896340736f;

    const float g0 = th[1], g1 = th[2], g2 = th[3], g3 = th[4];
    const float c0 = th[5], c1 = th[6], c2 = th[7], c3 = th[8];
    const float R    = 1.0f + th[10];
    const float iR   = 1.0f / R;                  // one-time accurate div
    const float bl   = th[0] * L2E;               // beta * log2(e)
    const float nR   = -R;
    const float sg   = th[9] * iR;                // sigma / R
    const float gi0 = g0 * iR, gi1 = g1 * iR, gi2 = g2 * iR, gi3 = g3 * iR;
    const float bi0 = c0 * iR, bi1 = c1 * iR, bi2 = c2 * iR, bi3 = c3 * iR;
    // E'-prep constants: E'_k = bl*(g_k - g0)*x3 + bl*(c_k - c0)
    const float bgd1 = bl * (g1 - g0), bgd2 = bl * (g2 - g0), bgd3 = bl * (g3 - g0);
    const float bcd1 = bl * (c1 - c0), bcd2 = bl * (c2 - c0), bcd3 = bl * (c3 - c0);

    const float4* ep4 = reinterpret_cast<const float4*>(eps + (size_t)b * T_CONST);
    float4*       o4  = reinterpret_cast<float4*>(out + (size_t)b * T_CONST);
    const int T8 = T_CONST / 8;                   // 8 steps per outer iter

    // carried state: x's and pre-clamped exponents for the first step.
    // t=0: x1=x2=0 -> U=0 -> A_k = 0 (p_k = 1).
    float x1 = 0.f, x2 = 0.f;
    float A1 = 0.f, A2 = 0.f, A3 = 0.f;

    // distance-2 (outer-iter) prefetch = 16 steps ahead; two float4 per iter
    float4 pfA0 = ep4[0], pfA1 = ep4[1];
    float4 pfB0 = ep4[2], pfB1 = ep4[3];

    for (int i = 0; i < T8; ++i) {
        float4 evA = pfA0, evB = pfA1;
        pfA0 = pfB0; pfA1 = pfB1;
        int nidx = (2 * i + 4 < 2 * T8) ? (2 * i + 4) : (2 * T8 - 2);
        pfB0 = ep4[nidx];
        pfB1 = ep4[nidx + 1];

        float es0 = evA.x * sg, es1 = evA.y * sg, es2 = evA.z * sg, es3 = evA.w * sg;
        float es4 = evB.x * sg, es5 = evB.y * sg, es6 = evB.z * sg, es7 = evB.w * sg;

        float xt0, xt1, xt2, xt3, xt4, xt5, xt6, xt7;
        float Ab1,Ab2,Ab3, Ac1,Ac2,Ac3, Ad1,Ad2,Ad3, Ae1,Ae2,Ae3;
        float Af1,Af2,Af3, Ag1,Ag2,Ag3, Ah1,Ah2,Ah3;

        BH_STEP(es0, x1,  x2,  A1,A2,A3,    xt0, Ab1,Ab2,Ab3);
        BH_STEP(es1, xt0, x1,  Ab1,Ab2,Ab3, xt1, Ac1,Ac2,Ac3);
        BH_STEP(es2, xt1, xt0, Ac1,Ac2,Ac3, xt2, Ad1,Ad2,Ad3);
        BH_STEP(es3, xt2, xt1, Ad1,Ad2,Ad3, xt3, Ae1,Ae2,Ae3);
        BH_STEP(es4, xt3, xt2, Ae1,Ae2,Ae3, xt4, Af1,Af2,Af3);
        BH_STEP(es5, xt4, xt3, Af1,Af2,Af3, xt5, Ag1,Ag2,Ag3);
        BH_STEP(es6, xt5, xt4, Ag1,Ag2,Ag3, xt6, Ah1,Ah2,Ah3);
        BH_STEP(es7, xt6, xt5, Ah1,Ah2,Ah3, xt7, A1,A2,A3);

        x2 = xt6;
        x1 = xt7;

        o4[2 * i]     = make_float4(xt0, xt1, xt2, xt3);
        o4[2 * i + 1] = make_float4(xt4, xt5, xt6, xt7);
    }
}

extern "C" void kernel_launch(void* const* d_in, const int* in_sizes, int n_in,
                              void* d_out, int out_size)
{
    const float* theta = (const float*)d_in[0];   // (B, 11) float32
    const float* eps   = (const float*)d_in[1];   // (B, T)  float32
    float*       out   = (float*)d_out;           // (B, T)  float32

    bh_kernel<<<B_CONST / 32, 32>>>(theta, eps, out);
}